// round 8
// baseline (speedup 1.0000x reference)
#include <cuda_runtime.h>

#define B_SZ 4096
#define T_SZ 2048

typedef unsigned long long u64;

__device__ int g_counter;
__device__ int g_order[B_SZ];

// ---------------- fused scheduling prologue: counting sort (descending length) ----
__global__ __launch_bounds__(1024)
void sort_kernel(const int* __restrict__ lengths)
{
    __shared__ int hist[2048];
    const int tid = threadIdx.x;

    hist[tid] = 0; hist[tid + 1024] = 0;
    __syncthreads();

    for (int i = tid; i < B_SZ; i += 1024)
        atomicAdd(&hist[T_SZ - lengths[i]], 1);
    __syncthreads();

    const int o0 = hist[tid], o1 = hist[tid + 1024];
    for (int off = 1; off < 2048; off <<= 1) {
        int v0 = hist[tid]        + ((tid        >= off) ? hist[tid - off]        : 0);
        int v1 = hist[tid + 1024] + ((tid + 1024 >= off) ? hist[tid + 1024 - off] : 0);
        __syncthreads();
        hist[tid] = v0; hist[tid + 1024] = v1;
        __syncthreads();
    }
    hist[tid]        -= o0;          // exclusive prefix = start offsets
    hist[tid + 1024] -= o1;
    __syncthreads();

    for (int i = tid; i < B_SZ; i += 1024) {
        int pos = atomicAdd(&hist[T_SZ - lengths[i]], 1);
        g_order[pos] = i;
    }
    if (tid == 0) g_counter = 0;
}

// ---------------- math helpers ---------------------------------------------------
__device__ __forceinline__ float fast_ex2(float x) {
    float r; asm("ex2.approx.f32 %0, %1;" : "=f"(r) : "f"(x)); return r;
}
__device__ __forceinline__ float fast_rcp(float x) {
    float r; asm("rcp.approx.f32 %0, %1;" : "=f"(r) : "f"(x)); return r;
}
__device__ __forceinline__ float fast_tanh(float x) {
    float r; asm("tanh.approx.f32 %0, %1;" : "=f"(r) : "f"(x)); return r;
}
__device__ __forceinline__ float sigmoid_(float x) {          // head only (exact-ish)
    return fast_rcp(1.0f + fast_ex2(-1.44269504f * x));
}
__device__ __forceinline__ u64 ffma2(u64 a, u64 b, u64 c) {
    u64 d; asm("fma.rn.f32x2 %0, %1, %2, %3;" : "=l"(d) : "l"(a), "l"(b), "l"(c));
    return d;
}
__device__ __forceinline__ u64 add2(u64 a, u64 b) {
    u64 d; asm("add.rn.f32x2 %0, %1, %2;" : "=l"(d) : "l"(a), "l"(b));
    return d;
}
__device__ __forceinline__ u64 pack2(float lo, float hi) {
    u64 r; asm("mov.b64 %0, {%1, %2};" : "=l"(r) : "f"(lo), "f"(hi)); return r;
}
__device__ __forceinline__ void unpack2(u64 v, float& lo, float& hi) {
    asm("mov.b64 {%0, %1}, %2;" : "=f"(lo), "=f"(hi) : "l"(v));
}

// ---------------- main persistent kernel -----------------------------------------
// Gate-pair layout: accumulate (i,f) and (g,o) as f32x2 with h DUPLICATED in smem,
// so no horizontal adds are needed. Sigmoid args pre-scaled by 0.5 (sigma(v) =
// 0.5 + 0.5*tanh(v/2)); tanh args unscaled; all activations via tanh.approx.
__global__ __launch_bounds__(128, 3)
void bilstm_kernel(const float* __restrict__ x,
                   const int* __restrict__ lengths,
                   const float* __restrict__ w_ih,
                   const float* __restrict__ w_hh,
                   const float* __restrict__ b_ih,
                   const float* __restrict__ b_hh,
                   const float* __restrict__ fc_w,
                   const float* __restrict__ fc_b,
                   const float* __restrict__ fc2_w,
                   const float* __restrict__ fc2_b,
                   float* __restrict__ out)
{
    const int lane = threadIdx.x & 31;
    const int wrp  = threadIdx.x >> 5;

    // h broadcast, duplicated per element: hsh[warp][buf][k] = (h_k, h_k)
    __shared__ __align__(16) float2 hsh[4][2][32];
    // x chunks, duplicated: xs[warp][ring][i] = (x, x)
    __shared__ __align__(16) float2 xs[4][2][32];

    // weights as gate pairs: wif[k] = (0.5*W_i[k], 0.5*W_f[k]),
    //                        wgo[k] = (1.0*W_g[k], 0.5*W_o[k])
    u64 wif[32], wgo[32];
    u64 bif, bgo;            // (w_ih pair) handled separately from (bias pair)
    u64 xif, xgo;            // scaled w_ih pairs
    {
        const int ri = lane, rf = 32 + lane, rg = 64 + lane, ro = 96 + lane;
        const float si = 0.5f, sf = 0.5f, sg = 1.0f, so = 0.5f;
#pragma unroll
        for (int k = 0; k < 32; ++k) {
            wif[k] = pack2(si * __ldg(w_hh + ri * 32 + k),
                           sf * __ldg(w_hh + rf * 32 + k));
            wgo[k] = pack2(sg * __ldg(w_hh + rg * 32 + k),
                           so * __ldg(w_hh + ro * 32 + k));
        }
        xif = pack2(si * __ldg(w_ih + ri), sf * __ldg(w_ih + rf));
        xgo = pack2(sg * __ldg(w_ih + rg), so * __ldg(w_ih + ro));
        bif = pack2(si * (__ldg(b_ih + ri) + __ldg(b_hh + ri)),
                    sf * (__ldg(b_ih + rf) + __ldg(b_hh + rf)));
        bgo = pack2(sg * (__ldg(b_ih + rg) + __ldg(b_hh + rg)),
                    so * (__ldg(b_ih + ro) + __ldg(b_hh + ro)));
    }

    const unsigned FULL = 0xffffffffu;

    float h, cc;

    // One LSTM step. cb: x ring buffer, i: index in chunk, pb: h buffer.
    auto lstm_step = [&](int cb, int i, int pb) {
        hsh[wrp][pb][lane] = make_float2(h, h);
        __syncwarp();

        // acc init: bias + x * w_ih  (x duplicated pair from smem)
        const u64 xx = *reinterpret_cast<const u64*>(&xs[wrp][cb][i]);
        u64 aif0 = ffma2(xx, xif, bif);
        u64 ago0 = ffma2(xx, xgo, bgo);
        u64 aif1 = 0, ago1 = 0;      // second accumulator pair (zero-init cheap)

        const ulonglong2* hp = reinterpret_cast<const ulonglong2*>(&hsh[wrp][pb][0]);
#pragma unroll
        for (int q = 0; q < 8; ++q) {            // k = 2q, 2q+1
            const ulonglong2 hv = hp[q];         // ((h,h),(h',h')) LDS.128 broadcast
            aif0 = ffma2(hv.x, wif[2 * q], aif0);
            ago0 = ffma2(hv.x, wgo[2 * q], ago0);
            aif0 = ffma2(hv.y, wif[2 * q + 1], aif0);
            ago0 = ffma2(hv.y, wgo[2 * q + 1], ago0);
        }
#pragma unroll
        for (int q = 8; q < 16; ++q) {
            const ulonglong2 hv = hp[q];
            aif1 = ffma2(hv.x, wif[2 * q], aif1);
            ago1 = ffma2(hv.x, wgo[2 * q], ago1);
            aif1 = ffma2(hv.y, wif[2 * q + 1], aif1);
            ago1 = ffma2(hv.y, wgo[2 * q + 1], ago1);
        }
        const u64 aif = add2(aif0, aif1);
        const u64 ago = add2(ago0, ago1);

        float gi, gf, gg, go;
        unpack2(aif, gi, gf);        // pre-scaled: gi = 0.5*raw_i, gf = 0.5*raw_f
        unpack2(ago, gg, go);        // gg = raw_g, go = 0.5*raw_o

        const float iv = fmaf(0.5f, fast_tanh(gi), 0.5f);   // sigmoid(raw_i)
        const float fv = fmaf(0.5f, fast_tanh(gf), 0.5f);
        const float gv = fast_tanh(gg);
        const float ov = fmaf(0.5f, fast_tanh(go), 0.5f);

        cc = fmaf(fv, cc, iv * gv);
        h = ov * fast_tanh(cc);
    };

    for (;;) {
        int s0 = 0;
        if (lane == 0) s0 = atomicAdd(&g_counter, 1);
        s0 = __shfl_sync(FULL, s0, 0);
        if (s0 >= B_SZ) break;

        const int idx = g_order[s0];
        const int len = __ldg(lengths + idx);
        const float* xb = x + (size_t)idx * T_SZ;

        h = 0.0f; cc = 0.0f;

        int t = len - 1;
        const int c0 = t >> 5;
        // stage first (possibly partial) chunk duplicated; prefetch next
        {
            const float v = __ldg(xb + (c0 << 5) + lane);
            xs[wrp][c0 & 1][lane] = make_float2(v, v);
        }
        float pend = (c0 > 0) ? __ldg(xb + ((c0 - 1) << 5) + lane) : 0.0f;

        int pb = 0;

        // peel: partial first chunk
#pragma unroll 1
        for (int i = t & 31; i >= 0; --i) {
            lstm_step(c0 & 1, i, pb);
            pb ^= 1;
        }

        // full chunks: branch-free steps; 1 STS.64 + 1 LDG per 32 steps
#pragma unroll 1
        for (int c = c0 - 1; c >= 0; --c) {
            xs[wrp][c & 1][lane] = make_float2(pend, pend);
            pend = (c > 0) ? __ldg(xb + ((c - 1) << 5) + lane) : 0.0f;
#pragma unroll 2
            for (int i = 31; i >= 0; --i) {
                lstm_step(c & 1, i, pb);
                pb ^= 1;
            }
        }

        // ---- FC head: sigmoid(fc2(elu(fc1(h)))) ----
        __syncwarp();
        hsh[wrp][0][lane] = make_float2(h, h);
        __syncwarp();

        float o1 = __ldg(fc_b + lane);
        float o2 = __ldg(fc_b + lane + 32);
#pragma unroll
        for (int k = 0; k < 32; ++k) {
            const float hk = hsh[wrp][0][k].x;
            o1 = fmaf(hk, __ldg(fc_w + lane * 32 + k), o1);
            o2 = fmaf(hk, __ldg(fc_w + (lane + 32) * 32 + k), o2);
        }
        o1 = (o1 > 0.0f) ? o1 : (fast_ex2(1.44269504f * o1) - 1.0f);  // ELU
        o2 = (o2 > 0.0f) ? o2 : (fast_ex2(1.44269504f * o2) - 1.0f);

        float part = o1 * __ldg(fc2_w + lane) + o2 * __ldg(fc2_w + lane + 32);
#pragma unroll
        for (int d = 16; d >= 1; d >>= 1)
            part += __shfl_xor_sync(FULL, part, d);

        if (lane == 0)
            out[idx] = sigmoid_(part + __ldg(fc2_b));

        __syncwarp();
    }
}

extern "C" void kernel_launch(void* const* d_in, const int* in_sizes, int n_in,
                              void* d_out, int out_size)
{
    const float* x       = (const float*)d_in[0];
    const int*   lengths = (const int*)  d_in[1];
    const float* w_ih    = (const float*)d_in[2];
    const float* w_hh    = (const float*)d_in[3];
    const float* b_ih    = (const float*)d_in[4];
    const float* b_hh    = (const float*)d_in[5];
    const float* fc_w    = (const float*)d_in[6];
    const float* fc_b    = (const float*)d_in[7];
    const float* fc2_w   = (const float*)d_in[8];
    const float* fc2_b   = (const float*)d_in[9];
    float* out = (float*)d_out;

    sort_kernel<<<1, 1024>>>(lengths);
    // 148 SMs x 3 resident blocks (12 warps/SM); atomic queue + LPT order.
    bilstm_kernel<<<444, 128>>>(x, lengths, w_ih, w_hh, b_ih, b_hh,
                                fc_w, fc_b, fc2_w, fc2_b, out);
}

// round 9
// speedup vs baseline: 2.3981x; 2.3981x over previous
#include <cuda_runtime.h>
#include <cuda_fp16.h>

#define B_SZ 4096
#define T_SZ 2048
typedef unsigned u32;

__device__ int g_order[B_SZ];

// ---------------- prologue: counting sort by descending length --------------------
__global__ __launch_bounds__(1024)
void sort_kernel(const int* __restrict__ lengths)
{
    __shared__ int hist[2048];
    const int tid = threadIdx.x;
    hist[tid] = 0; hist[tid + 1024] = 0;
    __syncthreads();
    for (int i = tid; i < B_SZ; i += 1024)
        atomicAdd(&hist[T_SZ - lengths[i]], 1);
    __syncthreads();
    const int o0 = hist[tid], o1 = hist[tid + 1024];
    for (int off = 1; off < 2048; off <<= 1) {
        int v0 = hist[tid]        + ((tid        >= off) ? hist[tid - off]        : 0);
        int v1 = hist[tid + 1024] + ((tid + 1024 >= off) ? hist[tid + 1024 - off] : 0);
        __syncthreads();
        hist[tid] = v0; hist[tid + 1024] = v1;
        __syncthreads();
    }
    hist[tid] -= o0; hist[tid + 1024] -= o1;
    __syncthreads();
    for (int i = tid; i < B_SZ; i += 1024) {
        int pos = atomicAdd(&hist[T_SZ - lengths[i]], 1);
        g_order[pos] = i;
    }
}

// ---------------- helpers ---------------------------------------------------------
__device__ __forceinline__ float fast_ex2(float x) {
    float r; asm("ex2.approx.f32 %0, %1;" : "=f"(r) : "f"(x)); return r;
}
__device__ __forceinline__ float fast_rcp(float x) {
    float r; asm("rcp.approx.f32 %0, %1;" : "=f"(r) : "f"(x)); return r;
}
__device__ __forceinline__ float fast_tanh(float x) {
    float r; asm("tanh.approx.f32 %0, %1;" : "=f"(r) : "f"(x)); return r;
}
__device__ __forceinline__ float sigmoid_(float x) {
    return fast_rcp(1.0f + fast_ex2(-1.44269504f * x));
}
__device__ __forceinline__ u32 pack_h2(float lo, float hi) {
    __half2 h = __floats2half2_rn(lo, hi);
    return *reinterpret_cast<u32*>(&h);
}
// D = A(16x16 f16,row) * B(16x8 f16,col) + D   (fp32 accum)
__device__ __forceinline__ void mma16816(float& d0, float& d1, float& d2, float& d3,
                                         u32 a0, u32 a1, u32 a2, u32 a3,
                                         u32 b0, u32 b1) {
    asm volatile(
        "mma.sync.aligned.m16n8k16.row.col.f32.f16.f16.f32 "
        "{%0,%1,%2,%3},{%4,%5,%6,%7},{%8,%9},{%0,%1,%2,%3};"
        : "+f"(d0), "+f"(d1), "+f"(d2), "+f"(d3)
        : "r"(a0), "r"(a1), "r"(a2), "r"(a3), "r"(b0), "r"(b1));
}

// ---------------- main kernel: 8 sequences per warp via HMMA ----------------------
// W_ext(128x48) f16 in regs; H_ext = [h(32); x; 1; 0...] f16 in smem per step.
// Gate rows: g*32 + j. m-tile mt = 2g + b covers rows 32g+16b .. +15.
// Scales folded: 0.5 for i,f,o (sigma(v)=0.5+0.5 tanh(v/2)); 1.0 for g.
__global__ __launch_bounds__(128)
void bilstm_mma_kernel(const float* __restrict__ x,
                       const int* __restrict__ lengths,
                       const float* __restrict__ w_ih,
                       const float* __restrict__ w_hh,
                       const float* __restrict__ b_ih,
                       const float* __restrict__ b_hh,
                       const float* __restrict__ fc_w,
                       const float* __restrict__ fc_b,
                       const float* __restrict__ fc2_w,
                       const float* __restrict__ fc2_b,
                       float* __restrict__ out)
{
    const int lane = threadIdx.x & 31;
    const int wid  = threadIdx.x >> 5;
    const int g4 = lane >> 2;        // 0..7 : B-frag col (seq) / A-frag row
    const int tq = lane & 3;         // 0..3 : k-pair / D-col pair

    // per-warp smem: h double-buffer (half, padded 40 half/seq) + x chunk (packed x,1)
    __shared__ u32 hbsh[4][2 * 8 * 20];
    __shared__ u32 xpsh[4][8 * 32];
    u32* hbS  = hbsh[wid];
    u32* xpkS = xpsh[wid];

    const int group = blockIdx.x * 4 + wid;      // 512 groups exactly

    int idxs[8];
#pragma unroll
    for (int r = 0; r < 8; ++r) idxs[r] = g_order[group * 8 + r];
    const int lenmax = __ldg(lengths + idxs[0]);                 // sorted desc
    const int lenA = __ldg(lengths + idxs[2 * tq]);              // my D-col seqs
    const int lenB = __ldg(lengths + idxs[2 * tq + 1]);

    // ---- A fragments (weights) ----
    const float scl[4] = {0.5f, 0.5f, 1.0f, 0.5f};
    u32 Afr[8][2][4];
    u32 A2f[8][2];
#pragma unroll
    for (int mt = 0; mt < 8; ++mt) {
        const int g = mt >> 1, bb = mt & 1;
        const float s = scl[g];
        const int R0 = g * 32 + bb * 16 + g4;
        const int R1 = R0 + 8;
#pragma unroll
        for (int kt = 0; kt < 2; ++kt) {
            const int c0 = kt * 16 + 2 * tq;
            Afr[mt][kt][0] = pack_h2(s * __ldg(w_hh + R0 * 32 + c0),
                                     s * __ldg(w_hh + R0 * 32 + c0 + 1));
            Afr[mt][kt][1] = pack_h2(s * __ldg(w_hh + R1 * 32 + c0),
                                     s * __ldg(w_hh + R1 * 32 + c0 + 1));
            Afr[mt][kt][2] = pack_h2(s * __ldg(w_hh + R0 * 32 + c0 + 8),
                                     s * __ldg(w_hh + R0 * 32 + c0 + 9));
            Afr[mt][kt][3] = pack_h2(s * __ldg(w_hh + R1 * 32 + c0 + 8),
                                     s * __ldg(w_hh + R1 * 32 + c0 + 9));
        }
        if (tq == 0) {   // kt=2 cols 32(w_ih),33(bias); other lanes' cols are zero
            A2f[mt][0] = pack_h2(s * __ldg(w_ih + R0),
                                 s * (__ldg(b_ih + R0) + __ldg(b_hh + R0)));
            A2f[mt][1] = pack_h2(s * __ldg(w_ih + R1),
                                 s * (__ldg(b_ih + R1) + __ldg(b_hh + R1)));
        } else { A2f[mt][0] = 0u; A2f[mt][1] = 0u; }
    }

    // zero h buffers (h0 = 0)
    for (int k = lane; k < 320; k += 32) hbS[k] = 0u;

    // states: st = bb*4 + rh*2 + sh -> seq 2*tq+sh, hidden j = 16*bb + g4 + 8*rh
    float hS[8], cS[8];
#pragma unroll
    for (int st = 0; st < 8; ++st) { hS[st] = 0.0f; cS[st] = 0.0f; }

    const int tmax = lenmax - 1;
    const int ctop = tmax >> 5;
    int pb = 0;

#pragma unroll 1
    for (int c = ctop; c >= 0; --c) {
        __syncwarp();                 // prior chunk's x reads done
#pragma unroll
        for (int r = 0; r < 8; ++r) {
            const float v = __ldg(x + (size_t)idxs[r] * T_SZ + (c << 5) + lane);
            xpkS[r * 32 + lane] = pack_h2(v, 1.0f);
        }
        __syncwarp();

        const int istart = (c == ctop) ? (tmax & 31) : 31;
#pragma unroll 1
        for (int i = istart; i >= 0; --i) {
            const int t = (c << 5) + i;

            // B fragments from h buffer pb
            const u32* hbp = hbS + pb * 160;
            const u32 b00 = hbp[g4 * 20 + tq];
            const u32 b01 = hbp[g4 * 20 + tq + 4];
            const u32 b10 = hbp[g4 * 20 + tq + 8];
            const u32 b11 = hbp[g4 * 20 + tq + 12];
            const u32 b20 = (tq == 0) ? xpkS[g4 * 32 + i] : 0u;

            float d[8][4];
#pragma unroll
            for (int mt = 0; mt < 8; ++mt) {
                d[mt][0] = 0.0f; d[mt][1] = 0.0f; d[mt][2] = 0.0f; d[mt][3] = 0.0f;
                mma16816(d[mt][0], d[mt][1], d[mt][2], d[mt][3],
                         Afr[mt][0][0], Afr[mt][0][1], Afr[mt][0][2], Afr[mt][0][3],
                         b00, b01);
                mma16816(d[mt][0], d[mt][1], d[mt][2], d[mt][3],
                         Afr[mt][1][0], Afr[mt][1][1], Afr[mt][1][2], Afr[mt][1][3],
                         b10, b11);
                mma16816(d[mt][0], d[mt][1], d[mt][2], d[mt][3],
                         A2f[mt][0], A2f[mt][1], 0u, 0u, b20, 0u);
            }

            // activations + state update + h writeback (buffer pb^1)
            half* hwp = reinterpret_cast<half*>(hbS + (pb ^ 1) * 160);
#pragma unroll
            for (int st = 0; st < 8; ++st) {
                const int sh = st & 1, rh = (st >> 1) & 1, bb = st >> 2;
                const int dreg = 2 * rh + sh;
                const float vi = d[bb][dreg];
                const float vf = d[2 + bb][dreg];
                const float vg = d[4 + bb][dreg];
                const float vo = d[6 + bb][dreg];
                const float I = fmaf(0.5f, fast_tanh(vi), 0.5f);
                const float F = fmaf(0.5f, fast_tanh(vf), 0.5f);
                const float G = fast_tanh(vg);
                const float O = fmaf(0.5f, fast_tanh(vo), 0.5f);
                const float cn = fmaf(F, cS[st], I * G);
                const float hn = O * fast_tanh(cn);
                const bool m = t < (sh ? lenB : lenA);
                cS[st] = m ? cn : cS[st];
                hS[st] = m ? hn : hS[st];
                hwp[(2 * tq + sh) * 40 + 16 * bb + g4 + 8 * rh] = __float2half(hS[st]);
            }
            __syncwarp();
            pb ^= 1;
        }
    }

    // ---- FC head: sigmoid(fc2(elu(fc1(h_n)))) for the 8 group sequences ----
    float* hf = reinterpret_cast<float*>(xpkS);   // reuse x buffer: hf[s*32 + j]
    __syncwarp();
#pragma unroll
    for (int st = 0; st < 8; ++st) {
        const int sh = st & 1, rh = (st >> 1) & 1, bb = st >> 2;
        hf[(2 * tq + sh) * 32 + 16 * bb + g4 + 8 * rh] = hS[st];
    }
    __syncwarp();

#pragma unroll
    for (int s = 0; s < 8; ++s) {
        float o1 = __ldg(fc_b + lane);
        float o2 = __ldg(fc_b + lane + 32);
#pragma unroll
        for (int k = 0; k < 32; ++k) {
            const float hk = hf[s * 32 + k];
            o1 = fmaf(hk, __ldg(fc_w + lane * 32 + k), o1);
            o2 = fmaf(hk, __ldg(fc_w + (lane + 32) * 32 + k), o2);
        }
        o1 = (o1 > 0.0f) ? o1 : (fast_ex2(1.44269504f * o1) - 1.0f);
        o2 = (o2 > 0.0f) ? o2 : (fast_ex2(1.44269504f * o2) - 1.0f);
        float part = o1 * __ldg(fc2_w + lane) + o2 * __ldg(fc2_w + lane + 32);
#pragma unroll
        for (int dd = 16; dd >= 1; dd >>= 1)
            part += __shfl_xor_sync(0xffffffffu, part, dd);
        if (lane == 0)
            out[idxs[s]] = sigmoid_(part + __ldg(fc2_b));
    }
}

extern "C" void kernel_launch(void* const* d_in, const int* in_sizes, int n_in,
                              void* d_out, int out_size)
{
    const float* x       = (const float*)d_in[0];
    const int*   lengths = (const int*)  d_in[1];
    const float* w_ih    = (const float*)d_in[2];
    const float* w_hh    = (const float*)d_in[3];
    const float* b_ih    = (const float*)d_in[4];
    const float* b_hh    = (const float*)d_in[5];
    const float* fc_w    = (const float*)d_in[6];
    const float* fc_b    = (const float*)d_in[7];
    const float* fc2_w   = (const float*)d_in[8];
    const float* fc2_b   = (const float*)d_in[9];
    float* out = (float*)d_out;

    sort_kernel<<<1, 1024>>>(lengths);
    // 512 groups of 8 sorted-adjacent sequences; 4 warps/block -> 1 warp/SMSP.
    bilstm_mma_kernel<<<128, 128>>>(x, lengths, w_ih, w_hh, b_ih, b_hh,
                                    fc_w, fc_b, fc2_w, fc2_b, out);
}

// round 10
// speedup vs baseline: 2.6267x; 1.0953x over previous
#include <cuda_runtime.h>
#include <cuda_fp16.h>

#define B_SZ 4096
#define T_SZ 2048
#define NGROUPS 512
typedef unsigned u32;

__device__ int g_counter;
__device__ int g_order[B_SZ];

// ---------------- prologue: counting sort by descending length --------------------
__global__ __launch_bounds__(1024)
void sort_kernel(const int* __restrict__ lengths)
{
    __shared__ int hist[2048];
    const int tid = threadIdx.x;
    hist[tid] = 0; hist[tid + 1024] = 0;
    __syncthreads();
    for (int i = tid; i < B_SZ; i += 1024)
        atomicAdd(&hist[T_SZ - lengths[i]], 1);
    __syncthreads();
    const int o0 = hist[tid], o1 = hist[tid + 1024];
    for (int off = 1; off < 2048; off <<= 1) {
        int v0 = hist[tid]        + ((tid        >= off) ? hist[tid - off]        : 0);
        int v1 = hist[tid + 1024] + ((tid + 1024 >= off) ? hist[tid + 1024 - off] : 0);
        __syncthreads();
        hist[tid] = v0; hist[tid + 1024] = v1;
        __syncthreads();
    }
    hist[tid] -= o0; hist[tid + 1024] -= o1;
    __syncthreads();
    for (int i = tid; i < B_SZ; i += 1024) {
        int pos = atomicAdd(&hist[T_SZ - lengths[i]], 1);
        g_order[pos] = i;
    }
    if (tid == 0) g_counter = 0;
}

// ---------------- helpers ---------------------------------------------------------
__device__ __forceinline__ float fast_ex2(float x) {
    float r; asm("ex2.approx.f32 %0, %1;" : "=f"(r) : "f"(x)); return r;
}
__device__ __forceinline__ float fast_rcp(float x) {
    float r; asm("rcp.approx.f32 %0, %1;" : "=f"(r) : "f"(x)); return r;
}
__device__ __forceinline__ float fast_tanh(float x) {
    float r; asm("tanh.approx.f32 %0, %1;" : "=f"(r) : "f"(x)); return r;
}
__device__ __forceinline__ float sigmoid_(float x) {
    return fast_rcp(1.0f + fast_ex2(-1.44269504f * x));
}
__device__ __forceinline__ u32 pack_h2(float lo, float hi) {
    __half2 h = __floats2half2_rn(lo, hi);
    return *reinterpret_cast<u32*>(&h);
}
__device__ __forceinline__ u32 movm_t(u32 a) {     // 8x8 b16 register transpose
    u32 d; asm("movmatrix.sync.aligned.m8n8.trans.b16 %0, %1;" : "=r"(d) : "r"(a));
    return d;
}
// D = A(16x16 f16,row) * B(16x8 f16,col) + D   (fp32 accum)
__device__ __forceinline__ void mma16816(float& d0, float& d1, float& d2, float& d3,
                                         u32 a0, u32 a1, u32 a2, u32 a3,
                                         u32 b0, u32 b1) {
    asm volatile(
        "mma.sync.aligned.m16n8k16.row.col.f32.f16.f16.f32 "
        "{%0,%1,%2,%3},{%4,%5,%6,%7},{%8,%9},{%0,%1,%2,%3};"
        : "+f"(d0), "+f"(d1), "+f"(d2), "+f"(d3)
        : "r"(a0), "r"(a1), "r"(a2), "r"(a3), "r"(b0), "r"(b1));
}

// ---------------- main kernel: 8 sequences/warp via HMMA + movmatrix --------------
// W_ext(128x48) f16 in regs; H_ext = [h(32); x; 1] f16: h carried purely in
// registers across steps (movmatrix transpose), x via per-warp smem chunks.
// Gate rows g*32+j; m-tile mt = 2g+bb covers rows 32g+16bb..+15.
// Scales folded: 0.5 for i,f,o (sigma(v)=0.5+0.5 tanh(v/2)); 1.0 for g.
__global__ __launch_bounds__(128)
void bilstm_mma_kernel(const float* __restrict__ x,
                       const int* __restrict__ lengths,
                       const float* __restrict__ w_ih,
                       const float* __restrict__ w_hh,
                       const float* __restrict__ b_ih,
                       const float* __restrict__ b_hh,
                       const float* __restrict__ fc_w,
                       const float* __restrict__ fc_b,
                       const float* __restrict__ fc2_w,
                       const float* __restrict__ fc2_b,
                       float* __restrict__ out)
{
    const int lane = threadIdx.x & 31;
    const int wid  = threadIdx.x >> 5;
    const int g4 = lane >> 2;        // 0..7
    const int tq = lane & 3;         // 0..3

    // per-warp x chunk: packed (x, 1.0) halves, 8 seqs x 32 steps
    __shared__ u32 xpsh[4][8 * 32];
    u32* xpkS = xpsh[wid];

    // ---- A fragments (weights), loaded once ----
    const float scl[4] = {0.5f, 0.5f, 1.0f, 0.5f};
    u32 Afr[8][2][4];
    u32 A2f[8][2];
#pragma unroll
    for (int mt = 0; mt < 8; ++mt) {
        const int g = mt >> 1, bb = mt & 1;
        const float s = scl[g];
        const int R0 = g * 32 + bb * 16 + g4;
        const int R1 = R0 + 8;
#pragma unroll
        for (int kt = 0; kt < 2; ++kt) {
            const int c0 = kt * 16 + 2 * tq;
            Afr[mt][kt][0] = pack_h2(s * __ldg(w_hh + R0 * 32 + c0),
                                     s * __ldg(w_hh + R0 * 32 + c0 + 1));
            Afr[mt][kt][1] = pack_h2(s * __ldg(w_hh + R1 * 32 + c0),
                                     s * __ldg(w_hh + R1 * 32 + c0 + 1));
            Afr[mt][kt][2] = pack_h2(s * __ldg(w_hh + R0 * 32 + c0 + 8),
                                     s * __ldg(w_hh + R0 * 32 + c0 + 9));
            Afr[mt][kt][3] = pack_h2(s * __ldg(w_hh + R1 * 32 + c0 + 8),
                                     s * __ldg(w_hh + R1 * 32 + c0 + 9));
        }
        if (tq == 0) {   // k-tile 2: col 32 = w_ih, col 33 = fused bias
            A2f[mt][0] = pack_h2(s * __ldg(w_ih + R0),
                                 s * (__ldg(b_ih + R0) + __ldg(b_hh + R0)));
            A2f[mt][1] = pack_h2(s * __ldg(w_ih + R1),
                                 s * (__ldg(b_ih + R1) + __ldg(b_hh + R1)));
        } else { A2f[mt][0] = 0u; A2f[mt][1] = 0u; }
    }

    const unsigned FULL = 0xffffffffu;

    // ---- persistent work queue over sorted 8-seq groups ----
    for (;;) {
        int s0 = 0;
        if (lane == 0) s0 = atomicAdd(&g_counter, 1);
        s0 = __shfl_sync(FULL, s0, 0);
        if (s0 >= NGROUPS) break;

        int idxs[8];
#pragma unroll
        for (int r = 0; r < 8; ++r) idxs[r] = g_order[s0 * 8 + r];
        const int lenmax = __ldg(lengths + idxs[0]);          // sorted desc
        const int lenA = __ldg(lengths + idxs[2 * tq]);       // my D-col seqs
        const int lenB = __ldg(lengths + idxs[2 * tq + 1]);

        // states: st = bb*4 + rh*2 + sh -> seq 2*tq+sh, hidden j = 16*bb + g4 + 8*rh
        float hS[8], cS[8];
#pragma unroll
        for (int st = 0; st < 8; ++st) { hS[st] = 0.0f; cS[st] = 0.0f; }

        const int tmax = lenmax - 1;
        const int ctop = tmax >> 5;

#pragma unroll 1
        for (int c = ctop; c >= 0; --c) {
            __syncwarp();             // prior chunk's x reads done
#pragma unroll
            for (int r = 0; r < 8; ++r) {
                const float v = __ldg(x + (size_t)idxs[r] * T_SZ + (c << 5) + lane);
                xpkS[r * 32 + lane] = pack_h2(v, 1.0f);
            }
            __syncwarp();

            const int istart = (c == ctop) ? (tmax & 31) : 31;
#pragma unroll 2
            for (int i = istart; i >= 0; --i) {
                const int t = (c << 5) + i;

                // B fragments: register-space transpose of h (no smem)
                const u32 b00 = movm_t(pack_h2(hS[0], hS[1]));   // j 0..7
                const u32 b01 = movm_t(pack_h2(hS[2], hS[3]));   // j 8..15
                const u32 b10 = movm_t(pack_h2(hS[4], hS[5]));   // j 16..23
                const u32 b11 = movm_t(pack_h2(hS[6], hS[7]));   // j 24..31
                const u32 xv  = xpkS[g4 * 32 + i];
                const u32 b20 = (tq == 0) ? xv : 0u;

                float d[8][4];
#pragma unroll
                for (int mt = 0; mt < 8; ++mt) {
                    d[mt][0] = 0.0f; d[mt][1] = 0.0f;
                    d[mt][2] = 0.0f; d[mt][3] = 0.0f;
                }

                // bb = 0 m-tiles first (mt even)
#pragma unroll
                for (int mt = 0; mt < 8; mt += 2) {
                    mma16816(d[mt][0], d[mt][1], d[mt][2], d[mt][3],
                             Afr[mt][0][0], Afr[mt][0][1], Afr[mt][0][2], Afr[mt][0][3],
                             b00, b01);
                    mma16816(d[mt][0], d[mt][1], d[mt][2], d[mt][3],
                             Afr[mt][1][0], Afr[mt][1][1], Afr[mt][1][2], Afr[mt][1][3],
                             b10, b11);
                    mma16816(d[mt][0], d[mt][1], d[mt][2], d[mt][3],
                             A2f[mt][0], A2f[mt][1], 0u, 0u, b20, 0u);
                }

                // activate bb=0 states (overlaps with bb=1 MMA issue below)
#pragma unroll
                for (int st = 0; st < 4; ++st) {
                    const int sh = st & 1, rh = (st >> 1) & 1;
                    const int dreg = 2 * rh + sh;
                    const float I = fmaf(0.5f, fast_tanh(d[0][dreg]), 0.5f);
                    const float F = fmaf(0.5f, fast_tanh(d[2][dreg]), 0.5f);
                    const float G = fast_tanh(d[4][dreg]);
                    const float O = fmaf(0.5f, fast_tanh(d[6][dreg]), 0.5f);
                    const float cn = fmaf(F, cS[st], I * G);
                    const float hn = O * fast_tanh(cn);
                    const bool m = t < (sh ? lenB : lenA);
                    cS[st] = m ? cn : cS[st];
                    hS[st] = m ? hn : hS[st];
                }

                // bb = 1 m-tiles (mt odd)
#pragma unroll
                for (int mt = 1; mt < 8; mt += 2) {
                    mma16816(d[mt][0], d[mt][1], d[mt][2], d[mt][3],
                             Afr[mt][0][0], Afr[mt][0][1], Afr[mt][0][2], Afr[mt][0][3],
                             b00, b01);
                    mma16816(d[mt][0], d[mt][1], d[mt][2], d[mt][3],
                             Afr[mt][1][0], Afr[mt][1][1], Afr[mt][1][2], Afr[mt][1][3],
                             b10, b11);
                    mma16816(d[mt][0], d[mt][1], d[mt][2], d[mt][3],
                             A2f[mt][0], A2f[mt][1], 0u, 0u, b20, 0u);
                }

#pragma unroll
                for (int st = 4; st < 8; ++st) {
                    const int sh = st & 1, rh = (st >> 1) & 1;
                    const int dreg = 2 * rh + sh;
                    const float I = fmaf(0.5f, fast_tanh(d[1][dreg]), 0.5f);
                    const float F = fmaf(0.5f, fast_tanh(d[3][dreg]), 0.5f);
                    const float G = fast_tanh(d[5][dreg]);
                    const float O = fmaf(0.5f, fast_tanh(d[7][dreg]), 0.5f);
                    const float cn = fmaf(F, cS[st], I * G);
                    const float hn = O * fast_tanh(cn);
                    const bool m = t < (sh ? lenB : lenA);
                    cS[st] = m ? cn : cS[st];
                    hS[st] = m ? hn : hS[st];
                }
            }
        }

        // ---- FC head: sigmoid(fc2(elu(fc1(h_n)))) for the 8 group sequences ----
        float* hf = reinterpret_cast<float*>(xpkS);   // reuse x buffer: hf[s*32+j]
        __syncwarp();
#pragma unroll
        for (int st = 0; st < 8; ++st) {
            const int sh = st & 1, rh = (st >> 1) & 1, bb = st >> 2;
            hf[(2 * tq + sh) * 32 + 16 * bb + g4 + 8 * rh] = hS[st];
        }
        __syncwarp();

#pragma unroll 1
        for (int s = 0; s < 8; ++s) {
            float o1 = __ldg(fc_b + lane);
            float o2 = __ldg(fc_b + lane + 32);
#pragma unroll
            for (int k = 0; k < 32; ++k) {
                const float hk = hf[s * 32 + k];
                o1 = fmaf(hk, __ldg(fc_w + lane * 32 + k), o1);
                o2 = fmaf(hk, __ldg(fc_w + (lane + 32) * 32 + k), o2);
            }
            o1 = (o1 > 0.0f) ? o1 : (fast_ex2(1.44269504f * o1) - 1.0f);
            o2 = (o2 > 0.0f) ? o2 : (fast_ex2(1.44269504f * o2) - 1.0f);
            float part = o1 * __ldg(fc2_w + lane) + o2 * __ldg(fc2_w + lane + 32);
#pragma unroll
            for (int dd = 16; dd >= 1; dd >>= 1)
                part += __shfl_xor_sync(FULL, part, dd);
            if (lane == 0)
                out[idxs[s]] = sigmoid_(part + __ldg(fc2_b));
        }
        __syncwarp();      // hf reads done before next group overwrites xpkS
    }
}

extern "C" void kernel_launch(void* const* d_in, const int* in_sizes, int n_in,
                              void* d_out, int out_size)
{
    const float* x       = (const float*)d_in[0];
    const int*   lengths = (const int*)  d_in[1];
    const float* w_ih    = (const float*)d_in[2];
    const float* w_hh    = (const float*)d_in[3];
    const float* b_ih    = (const float*)d_in[4];
    const float* b_hh    = (const float*)d_in[5];
    const float* fc_w    = (const float*)d_in[6];
    const float* fc_b    = (const float*)d_in[7];
    const float* fc2_w   = (const float*)d_in[8];
    const float* fc2_b   = (const float*)d_in[9];
    float* out = (float*)d_out;

    sort_kernel<<<1, 1024>>>(lengths);
    // 148 persistent blocks x 4 warps = 1 warp/SMSP; atomic queue over 512
    // LPT-sorted groups -> makespan = longest group's chain only.
    bilstm_mma_kernel<<<148, 128>>>(x, lengths, w_ih, w_hh, b_ih, b_hh,
                                    fc_w, fc_b, fc2_w, fc2_b, out);
}